// round 9
// baseline (speedup 1.0000x reference)
#include <cuda_runtime.h>
#include <cuda_fp16.h>
#include <cstdint>

// VectorQuantizerEMA: N=16384 tokens, K=8192 codes, D=64.
// Outputs (fp32, concat): discrete[N*K], quantized[N*D], new_count[K],
// new_weight[K*D], new_codebook[K*D].

#define NTOK   16384
#define KCODES 8192
#define DIM    64
#define TM     128
#define TN     128
#define NCH    (KCODES / TN)   // 64
#define DECAYF 0.99f
#define OMDF   0.01f
#define EPSV   1e-5f
#define BATCHF 32.0f

// smem layout (bytes): 3-buffer B ring (fp16) + x staging (reused for reduction)
#define OFF_BUF(i) ((i) * 16384)
#define OFF_X      49152          // x fp16 16KB; reused as reduction scratch at the end
#define SMEM_BYTES 66560

// ---------------- device scratch ----------------
__device__ __align__(128) __half g_cbh[KCODES * DIM];   // fp16 codebook (screening)
__device__ float g_cnorm[KCODES];
__device__ float g_cnt[KCODES];
__device__ float g_wsum[KCODES * DIM];

// ---------------- PTX helpers (base-target legal) ----------------
__device__ __forceinline__ uint32_t smem_u32(const void* p) {
    uint32_t a;
    asm("{ .reg .u64 t; cvta.to.shared.u64 t, %1; cvt.u32.u64 %0, t; }" : "=r"(a) : "l"(p));
    return a;
}
__device__ __forceinline__ void ldsm4(uint32_t* r, uint32_t addr) {
    asm volatile("ldmatrix.sync.aligned.m8n8.x4.shared.b16 {%0,%1,%2,%3}, [%4];"
                 : "=r"(r[0]), "=r"(r[1]), "=r"(r[2]), "=r"(r[3]) : "r"(addr));
}
// fp16 in, fp16 accum (2-reg C/D): the fast legacy-HMMA variant
__device__ __forceinline__ void mma16816h(uint32_t* c, const uint32_t* a, uint32_t b0, uint32_t b1) {
    asm volatile("mma.sync.aligned.m16n8k16.row.col.f16.f16.f16.f16 "
                 "{%0,%1}, {%2,%3,%4,%5}, {%6,%7}, {%0,%1};"
                 : "+r"(c[0]), "+r"(c[1])
                 : "r"(a[0]), "r"(a[1]), "r"(a[2]), "r"(a[3]), "r"(b0), "r"(b1));
}
__device__ __forceinline__ void cp16(uint32_t dst, const void* src) {
    asm volatile("cp.async.cg.shared.global [%0], [%1], 16;" :: "r"(dst), "l"(src));
}
#define CP_COMMIT() asm volatile("cp.async.commit_group;" ::: "memory")
#define CP_WAIT1()  asm volatile("cp.async.wait_group 1;" ::: "memory")

__device__ __forceinline__ void ins2(float& V1, int& K1, float& V2, int& K2, float v, int k) {
    if (v < V1) { V2 = V1; K2 = K1; V1 = v; K1 = k; }
    else if (v < V2) { V2 = v; K2 = k; }
}
__device__ __forceinline__ void ins4(float* V, int* KI, float v, int k) {
    if (v < V[3]) {
        if (v < V[1]) {
            V[3] = V[2]; KI[3] = KI[2]; V[2] = V[1]; KI[2] = KI[1];
            if (v < V[0]) { V[1] = V[0]; KI[1] = KI[0]; V[0] = v; KI[0] = k; }
            else { V[1] = v; KI[1] = k; }
        } else {
            if (v < V[2]) { V[3] = V[2]; KI[3] = KI[2]; V[2] = v; KI[2] = k; }
            else { V[3] = v; KI[3] = k; }
        }
    }
}
__device__ __forceinline__ float dotrow(const float* xr, const float* cr) {
    float s = 0.f;
#pragma unroll
    for (int j = 0; j < 16; j++) {
        float4 a = ((const float4*)xr)[j];
        float4 b = ((const float4*)cr)[j];
        s += a.x * b.x + a.y * b.y + a.z * b.z + a.w * b.w;
    }
    return s;
}

// Stage one 128-code chunk (fp16, 16KB) into a smem ring buffer, SW128-swizzled.
__device__ __forceinline__ void stage_chunk(uint32_t sb, int chunk, uint32_t bufoff, int tid) {
    const char* src = (const char*)g_cbh + (size_t)chunk * 16384;
#pragma unroll
    for (int i = 0; i < 4; i++) {
        int gg = tid + i * 256;          // 0..1023 uint4s
        int row = gg >> 3, c = gg & 7;
        uint32_t dst = sb + bufoff + row * 128 + ((c * 16) ^ ((row & 7) << 4));
        cp16(dst, src + gg * 16);
    }
}

// ---------------- kernel 0: norms, fp16 cast, zero accumulators ----------------
__global__ void vq_prep(const float* __restrict__ cb) {
    int g = blockIdx.x * blockDim.x + threadIdx.x;   // KCODES*DIM threads
    float v = cb[g];
    g_cbh[g] = __float2half_rn(v);
    g_wsum[g] = 0.0f;
    if (g < KCODES) {
        g_cnt[g] = 0.0f;
        const float4* r = (const float4*)(cb + (size_t)g * DIM);
        float s = 0.0f;
#pragma unroll
        for (int j = 0; j < 16; j++) {
            float4 q = r[j];
            s += q.x * q.x + q.y * q.y + q.z * q.z + q.w * q.w;
        }
        g_cnorm[g] = s;
    }
}

// ---------------- kernel 1: fp16 screening GEMM + top-4 exact rescue + outputs ----------------
extern "C" __global__ void __launch_bounds__(256)
vq_main(const float* __restrict__ x, const float* __restrict__ cb,
        float* __restrict__ discrete, float* __restrict__ quantized) {
    extern __shared__ char smem[];
    const uint32_t sb = smem_u32(smem);
    const int tid = threadIdx.x, lane = tid & 31, wid = tid >> 5;
    const int mw = wid >> 1, nc = wid & 1;           // 4 m-rows x 2 n-cols of warps
    const int mbase = mw * 32, nbase = nc * 64;
    const int m0 = blockIdx.x * TM;
    const int qid = lane & 3;

    // ---- stage x tile: fp32 -> fp16, SW128 rows of 128B ----
    for (int i = tid; i < TM * DIM; i += 256) {
        int t = i >> 6, d = i & 63;
        float v = x[(size_t)(m0 + t) * DIM + d];
        uint32_t swz = (uint32_t)((d * 2) ^ ((t & 7) << 4));
        *(__half*)(smem + OFF_X + t * 128 + swz) = __float2half_rn(v);
    }
    // ---- prefetch first two B chunks ----
    stage_chunk(sb, 0, OFF_BUF(0), tid); CP_COMMIT();
    stage_chunk(sb, 1, OFF_BUF(1), tid); CP_COMMIT();
    __syncthreads();

    // ---- A fragments loaded once, held in regs ----
    uint32_t afr[2][4][4];   // [m-tile][k-step][reg]
#pragma unroll
    for (int mt = 0; mt < 2; mt++)
#pragma unroll
        for (int ks = 0; ks < 4; ks++) {
            int rowA = mbase + mt * 16 + (lane & 15);
            int byteA = ks * 32 + ((lane & 16) ? 16 : 0);
            ldsm4(afr[mt][ks], sb + OFF_X + rowA * 128 + (byteA ^ ((rowA & 7) << 4)));
        }

    // B ldsm per-lane invariants
    const uint32_t bRow = (uint32_t)(nbase + (lane & 7) + ((lane & 16) ? 8 : 0));
    const uint32_t bSwz = (bRow & 7) << 4;
    const uint32_t bByte = (lane & 8) ? 16u : 0u;

    // per-token-row top-2 trackers (4 rows per thread)
    float tv1[4], tv2[4];
    int   tk1[4], tk2[4];
#pragma unroll
    for (int i = 0; i < 4; i++) { tv1[i] = 3.4e38f; tv2[i] = 3.4e38f; tk1[i] = 0; tk2[i] = 0; }

    const float4 z4 = make_float4(0.f, 0.f, 0.f, 0.f);
    uint32_t acc[2][8][2];   // f16x2 accumulators

    for (int ch = 0; ch < NCH; ch++) {
        CP_WAIT1();
        __syncthreads();   // chunk ch visible; ring buffer (ch+2)%3 free since ch-1

        // stage-ahead: fill (ch+2)%3 while everyone reads ch%3
        if (ch + 2 < NCH) stage_chunk(sb, ch + 2, OFF_BUF((ch + 2) % 3), tid);
        CP_COMMIT();       // unconditional: keeps group counter aligned with chunk index

        // codebook norms for this warp's 64-column slice
        float2 nv[8];
        const float2* cnp = (const float2*)(g_cnorm + ch * TN + nbase);
#pragma unroll
        for (int nt = 0; nt < 8; nt++) nv[nt] = __ldg(&cnp[nt * 4 + qid]);

#pragma unroll
        for (int mt = 0; mt < 2; mt++)
#pragma unroll
            for (int nt = 0; nt < 8; nt++) { acc[mt][nt][0] = 0u; acc[mt][nt][1] = 0u; }

        const uint32_t bufb = OFF_BUF(ch % 3);
#pragma unroll
        for (int ks = 0; ks < 4; ks++) {
            uint32_t bh[4][4];
#pragma unroll
            for (int j = 0; j < 4; j++)
                ldsm4(bh[j], sb + bufb + (bRow + j * 16) * 128 + ((bByte + ks * 32) ^ bSwz));
#pragma unroll
            for (int mt = 0; mt < 2; mt++)
#pragma unroll
                for (int j = 0; j < 4; j++)
#pragma unroll
                    for (int h = 0; h < 2; h++)
                        mma16816h(acc[mt][j * 2 + h], afr[mt][ks], bh[j][h * 2], bh[j][h * 2 + 1]);
        }

        // interleaved streaming zero-fill: 64KB slice of this block's discrete slab
        {
            float4* zb = (float4*)(discrete + (size_t)m0 * KCODES) + (size_t)ch * 4096;
#pragma unroll
            for (int i = 0; i < 16; i++) __stcs(&zb[tid + i * 256], z4);
        }

        // gated epilogue: approx dist = ||c||^2 - 2*dot ; track top-2 per token row
        const int kc = ch * TN + nbase + qid * 2;
#pragma unroll
        for (int mt = 0; mt < 2; mt++)
#pragma unroll
            for (int nt = 0; nt < 8; nt++) {
                float2 f01 = __half22float2(*(const __half2*)&acc[mt][nt][0]);  // row r0: cols q,q+1
                float2 f23 = __half22float2(*(const __half2*)&acc[mt][nt][1]);  // row r0+8
                const int kk = kc + nt * 8;
                float d0 = fmaf(f01.x, -2.0f, nv[nt].x);
                float d1 = fmaf(f01.y, -2.0f, nv[nt].y);
                float d2 = fmaf(f23.x, -2.0f, nv[nt].x);
                float d3 = fmaf(f23.y, -2.0f, nv[nt].y);
                const int r0 = mt * 2, r1 = mt * 2 + 1;
                if (fminf(d0, d1) < tv2[r0]) {
                    ins2(tv1[r0], tk1[r0], tv2[r0], tk2[r0], d0, kk);
                    ins2(tv1[r0], tk1[r0], tv2[r0], tk2[r0], d1, kk + 1);
                }
                if (fminf(d2, d3) < tv2[r1]) {
                    ins2(tv1[r1], tk1[r1], tv2[r1], tk2[r1], d2, kk);
                    ins2(tv1[r1], tk1[r1], tv2[r1], tk2[r1], d3, kk + 1);
                }
            }
    }

    // ---- cross-thread reduction (reuse x staging smem) ----
    __syncthreads();
    float* sv = (float*)(smem + OFF_X);            // 2048 floats
    int*   sk = (int*)(smem + OFF_X + 8192);       // 2048 ints
    int*   sidx = (int*)(smem + OFF_X + 16384);    // 128 ints
#pragma unroll
    for (int tr = 0; tr < 4; tr++) {
        int s = ((wid * 32 + lane) * 4 + tr) * 2;
        sv[s] = tv1[tr]; sk[s] = tk1[tr];
        sv[s + 1] = tv2[tr]; sk[s + 1] = tk2[tr];
    }
    __syncthreads();

    if (tid < TM) {
        const int t = tid;
        const int tmw = t >> 5, rloc = t & 31;
        const int mt = rloc >> 4, sub = (rloc >> 3) & 1, l4 = rloc & 7;
        const int tr = mt * 2 + sub;
        float V[4] = {3.4e38f, 3.4e38f, 3.4e38f, 3.4e38f};
        int KI[4] = {0, 0, 0, 0};
#pragma unroll
        for (int ncc = 0; ncc < 2; ncc++)
#pragma unroll
            for (int c = 0; c < 4; c++) {
                int s = (((tmw * 2 + ncc) * 32 + l4 * 4 + c) * 4 + tr) * 2;
                ins4(V, KI, sv[s], sk[s]);
                ins4(V, KI, sv[s + 1], sk[s + 1]);
            }
        // exact fp32 rescue of approx top-4 -> argmin matches reference
        const float* xr = x + (size_t)(m0 + t) * DIM;
        float bd = 3.4e38f; int bk = 0x7fffffff;
#pragma unroll
        for (int i = 0; i < 4; i++) {
            int k = KI[i];
            float d = g_cnorm[k] - 2.0f * dotrow(xr, cb + (size_t)k * DIM);
            if (d < bd || (d == bd && k < bk)) { bd = d; bk = k; }
        }
        sidx[t] = bk;
        discrete[(size_t)(m0 + t) * KCODES + bk] = 1.0f;
        atomicAdd(&g_cnt[bk], 1.0f);
    }
    __syncthreads();

    // quantized gather + EMA weight numerator scatter
    for (int i = tid; i < TM * DIM; i += 256) {
        int t = i >> 6, d = i & 63;
        int k = sidx[t];
        quantized[(size_t)(m0 + t) * DIM + d] = cb[(size_t)k * DIM + d];
        atomicAdd(&g_wsum[k * DIM + d], x[(size_t)(m0 + t) * DIM + d]);
    }
}

// ---------------- kernel 2: EMA finalize ----------------
__global__ void vq_finalize(const float* __restrict__ ema_count,
                            const float* __restrict__ ema_weight,
                            float* __restrict__ ocount,
                            float* __restrict__ oweight,
                            float* __restrict__ ocb) {
    int i = blockIdx.x * blockDim.x + threadIdx.x;
    if (i >= KCODES * DIM) return;
    int k = i >> 6, d = i & 63;
    float cnt  = ema_count[k] * DECAYF + g_cnt[k] * OMDF;
    float norm = (cnt + EPSV) / (BATCHF + (float)KCODES * EPSV) * BATCHF;
    if (d == 0) ocount[k] = norm;
    float w = ema_weight[i] * DECAYF + g_wsum[i] * OMDF;
    oweight[i] = w;
    ocb[i]     = w / norm;
}

// ---------------- launch ----------------
extern "C" void kernel_launch(void* const* d_in, const int* in_sizes, int n_in,
                              void* d_out, int out_size) {
    const float* x  = (const float*)d_in[0];
    const float* cb = (const float*)d_in[1];
    const float* ec = (const float*)d_in[2];
    const float* ew = (const float*)d_in[3];

    float* out       = (float*)d_out;
    float* discrete  = out;                               // N*K
    float* quantized = discrete + (size_t)NTOK * KCODES;  // N*D
    float* ocount    = quantized + (size_t)NTOK * DIM;    // K
    float* oweight   = ocount + KCODES;                   // K*D
    float* ocb       = oweight + (size_t)KCODES * DIM;    // K*D

    vq_prep<<<(KCODES * DIM) / 256, 256>>>(cb);

    cudaFuncSetAttribute((const void*)vq_main,
                         cudaFuncAttributeMaxDynamicSharedMemorySize, SMEM_BYTES);
    vq_main<<<NTOK / TM, 256, SMEM_BYTES>>>(x, cb, discrete, quantized);

    vq_finalize<<<(KCODES * DIM + 255) / 256, 256>>>(ec, ew, ocount, oweight, ocb);
}

// round 10
// speedup vs baseline: 1.1227x; 1.1227x over previous
#include <cuda_runtime.h>
#include <cuda_fp16.h>
#include <cstdint>

// VectorQuantizerEMA: N=16384 tokens, K=8192 codes, D=64.
// Outputs (fp32, concat): discrete[N*K], quantized[N*D], new_count[K],
// new_weight[K*D], new_codebook[K*D].

#define NTOK   16384
#define KCODES 8192
#define DIM    64
#define TM     128
#define TN     128
#define NCH    (KCODES / TN)   // 64
#define NTHR   512
#define DECAYF 0.99f
#define OMDF   0.01f
#define EPSV   1e-5f
#define BATCHF 32.0f

// smem layout (bytes): 3-buffer B ring (fp16) + x staging
// After the mainloop the ring is reused as reduction scratch.
#define OFF_BUF(i) ((i) * 16384)
#define OFF_X      49152          // x fp16 16KB
#define SMEM_BYTES 66560

// ---------------- device scratch ----------------
__device__ __align__(128) __half g_cbh[KCODES * DIM];   // fp16 codebook (screening)
__device__ float g_cnorm[KCODES];
__device__ float g_cnt[KCODES];
__device__ float g_wsum[KCODES * DIM];

// ---------------- PTX helpers (base-target legal) ----------------
__device__ __forceinline__ uint32_t smem_u32(const void* p) {
    uint32_t a;
    asm("{ .reg .u64 t; cvta.to.shared.u64 t, %1; cvt.u32.u64 %0, t; }" : "=r"(a) : "l"(p));
    return a;
}
__device__ __forceinline__ void ldsm4(uint32_t* r, uint32_t addr) {
    asm volatile("ldmatrix.sync.aligned.m8n8.x4.shared.b16 {%0,%1,%2,%3}, [%4];"
                 : "=r"(r[0]), "=r"(r[1]), "=r"(r[2]), "=r"(r[3]) : "r"(addr));
}
// fp16 in, fp16 accum (2-reg C/D)
__device__ __forceinline__ void mma16816h(uint32_t* c, const uint32_t* a, uint32_t b0, uint32_t b1) {
    asm volatile("mma.sync.aligned.m16n8k16.row.col.f16.f16.f16.f16 "
                 "{%0,%1}, {%2,%3,%4,%5}, {%6,%7}, {%0,%1};"
                 : "+r"(c[0]), "+r"(c[1])
                 : "r"(a[0]), "r"(a[1]), "r"(a[2]), "r"(a[3]), "r"(b0), "r"(b1));
}
__device__ __forceinline__ void cp16(uint32_t dst, const void* src) {
    asm volatile("cp.async.cg.shared.global [%0], [%1], 16;" :: "r"(dst), "l"(src));
}
#define CP_COMMIT() asm volatile("cp.async.commit_group;" ::: "memory")
#define CP_WAIT1()  asm volatile("cp.async.wait_group 1;" ::: "memory")
#define CP_WAIT0()  asm volatile("cp.async.wait_group 0;" ::: "memory")

__device__ __forceinline__ void ins2(float& V1, int& K1, float& V2, int& K2, float v, int k) {
    if (v < V1) { V2 = V1; K2 = K1; V1 = v; K1 = k; }
    else if (v < V2) { V2 = v; K2 = k; }
}
__device__ __forceinline__ void ins4(float* V, int* KI, float v, int k) {
    if (v < V[3]) {
        if (v < V[1]) {
            V[3] = V[2]; KI[3] = KI[2]; V[2] = V[1]; KI[2] = KI[1];
            if (v < V[0]) { V[1] = V[0]; KI[1] = KI[0]; V[0] = v; KI[0] = k; }
            else { V[1] = v; KI[1] = k; }
        } else {
            if (v < V[2]) { V[3] = V[2]; KI[3] = KI[2]; V[2] = v; KI[2] = k; }
            else { V[3] = v; KI[3] = k; }
        }
    }
}
__device__ __forceinline__ float dotrow(const float* xr, const float* cr) {
    float s = 0.f;
#pragma unroll
    for (int j = 0; j < 16; j++) {
        float4 a = ((const float4*)xr)[j];
        float4 b = ((const float4*)cr)[j];
        s += a.x * b.x + a.y * b.y + a.z * b.z + a.w * b.w;
    }
    return s;
}

// Stage one 128-code chunk (fp16, 16KB) into a smem ring buffer, SW128-swizzled.
__device__ __forceinline__ void stage_chunk(uint32_t sb, int chunk, uint32_t bufoff, int tid) {
    const char* src = (const char*)g_cbh + (size_t)chunk * 16384;
#pragma unroll
    for (int i = 0; i < 2; i++) {
        int gg = tid + i * NTHR;         // 0..1023 uint4s
        int row = gg >> 3, c = gg & 7;
        uint32_t dst = sb + bufoff + row * 128 + ((c * 16) ^ ((row & 7) << 4));
        cp16(dst, src + gg * 16);
    }
}

// ---------------- kernel 0: norms, fp16 cast, zero accumulators ----------------
__global__ void vq_prep(const float* __restrict__ cb) {
    int g = blockIdx.x * blockDim.x + threadIdx.x;   // KCODES*DIM threads
    float v = cb[g];
    g_cbh[g] = __float2half_rn(v);
    g_wsum[g] = 0.0f;
    if (g < KCODES) {
        g_cnt[g] = 0.0f;
        const float4* r = (const float4*)(cb + (size_t)g * DIM);
        float s = 0.0f;
#pragma unroll
        for (int j = 0; j < 16; j++) {
            float4 q = r[j];
            s += q.x * q.x + q.y * q.y + q.z * q.z + q.w * q.w;
        }
        g_cnorm[g] = s;
    }
}

// ---------------- kernel 1: fp16 screening GEMM + top-4 exact rescue + outputs ----------------
// 512 threads = 16 warps in a 4m x 4n grid; per warp: 2 m-tiles(16) x 4 n8-tiles.
extern "C" __global__ void __launch_bounds__(NTHR)
vq_main(const float* __restrict__ x, const float* __restrict__ cb,
        float* __restrict__ discrete, float* __restrict__ quantized) {
    extern __shared__ char smem[];
    const uint32_t sb = smem_u32(smem);
    const int tid = threadIdx.x, lane = tid & 31, wid = tid >> 5;
    const int mw = wid >> 2, nc = wid & 3;           // 4 m-warps x 4 n-warps
    const int mbase = mw * 32, nbase = nc * 32;
    const int m0 = blockIdx.x * TM;
    const int qid = lane & 3;

    // ---- stage x tile: fp32 -> fp16, SW128 rows of 128B ----
    for (int i = tid; i < TM * DIM; i += NTHR) {
        int t = i >> 6, d = i & 63;
        float v = x[(size_t)(m0 + t) * DIM + d];
        uint32_t swz = (uint32_t)((d * 2) ^ ((t & 7) << 4));
        *(__half*)(smem + OFF_X + t * 128 + swz) = __float2half_rn(v);
    }
    // ---- prefetch first two B chunks ----
    stage_chunk(sb, 0, OFF_BUF(0), tid); CP_COMMIT();
    stage_chunk(sb, 1, OFF_BUF(1), tid); CP_COMMIT();
    __syncthreads();

    // ---- A fragments loaded once, held in regs ----
    uint32_t afr[2][4][4];   // [m-tile][k-step][reg]
#pragma unroll
    for (int mt = 0; mt < 2; mt++)
#pragma unroll
        for (int ks = 0; ks < 4; ks++) {
            int rowA = mbase + mt * 16 + (lane & 15);
            int byteA = ks * 32 + ((lane & 16) ? 16 : 0);
            ldsm4(afr[mt][ks], sb + OFF_X + rowA * 128 + (byteA ^ ((rowA & 7) << 4)));
        }

    // B ldsm per-lane invariants (two n16 groups per warp => bh[2])
    const uint32_t bRow = (uint32_t)(nbase + (lane & 7) + ((lane & 16) ? 8 : 0));
    const uint32_t bSwz = (bRow & 7) << 4;
    const uint32_t bByte = (lane & 8) ? 16u : 0u;

    // per-token-row top-2 trackers (4 rows per thread: 2 mt x 2 c-halves)
    float tv1[4], tv2[4];
    int   tk1[4], tk2[4];
#pragma unroll
    for (int i = 0; i < 4; i++) { tv1[i] = 3.4e38f; tv2[i] = 3.4e38f; tk1[i] = 0; tk2[i] = 0; }

    const float4 z4 = make_float4(0.f, 0.f, 0.f, 0.f);
    uint32_t acc[2][4][2];   // f16x2 accumulators [mt][nt][c-half]

    for (int ch = 0; ch < NCH; ch++) {
        CP_WAIT1();
        __syncthreads();   // chunk ch visible; ring buffer (ch+2)%3 free since ch-1

        // stage-ahead: fill (ch+2)%3 while everyone reads ch%3
        if (ch + 2 < NCH) stage_chunk(sb, ch + 2, OFF_BUF((ch + 2) % 3), tid);
        CP_COMMIT();       // unconditional: keeps group counter aligned with chunk index

        // codebook norms for this warp's 32-column slice
        float2 nv[4];
        const float2* cnp = (const float2*)(g_cnorm + ch * TN + nbase);
#pragma unroll
        for (int nt = 0; nt < 4; nt++) nv[nt] = __ldg(&cnp[nt * 4 + qid]);

#pragma unroll
        for (int mt = 0; mt < 2; mt++)
#pragma unroll
            for (int nt = 0; nt < 4; nt++) { acc[mt][nt][0] = 0u; acc[mt][nt][1] = 0u; }

        const uint32_t bufb = OFF_BUF(ch % 3);
#pragma unroll
        for (int ks = 0; ks < 4; ks++) {
            uint32_t bh[2][4];
#pragma unroll
            for (int j = 0; j < 2; j++)
                ldsm4(bh[j], sb + bufb + (bRow + j * 16) * 128 + ((bByte + ks * 32) ^ bSwz));
#pragma unroll
            for (int mt = 0; mt < 2; mt++)
#pragma unroll
                for (int j = 0; j < 2; j++)
#pragma unroll
                    for (int h = 0; h < 2; h++)
                        mma16816h(acc[mt][j * 2 + h], afr[mt][ks], bh[j][h * 2], bh[j][h * 2 + 1]);
        }

        // interleaved streaming zero-fill: 64KB slice of this block's discrete slab
        {
            float4* zb = (float4*)(discrete + (size_t)m0 * KCODES) + (size_t)ch * 4096;
#pragma unroll
            for (int i = 0; i < 8; i++) __stcs(&zb[tid + i * NTHR], z4);
        }

        // gated epilogue: approx dist = ||c||^2 - 2*dot ; track top-2 per token row
        const int kc = ch * TN + nbase + qid * 2;
#pragma unroll
        for (int mt = 0; mt < 2; mt++)
#pragma unroll
            for (int nt = 0; nt < 4; nt++) {
                float2 f01 = __half22float2(*(const __half2*)&acc[mt][nt][0]);  // row r, cols q,q+1
                float2 f23 = __half22float2(*(const __half2*)&acc[mt][nt][1]);  // row r+8
                const int kk = kc + nt * 8;
                float d0 = fmaf(f01.x, -2.0f, nv[nt].x);
                float d1 = fmaf(f01.y, -2.0f, nv[nt].y);
                float d2 = fmaf(f23.x, -2.0f, nv[nt].x);
                float d3 = fmaf(f23.y, -2.0f, nv[nt].y);
                const int r0 = mt * 2, r1 = mt * 2 + 1;
                if (fminf(d0, d1) < tv2[r0]) {
                    ins2(tv1[r0], tk1[r0], tv2[r0], tk2[r0], d0, kk);
                    ins2(tv1[r0], tk1[r0], tv2[r0], tk2[r0], d1, kk + 1);
                }
                if (fminf(d2, d3) < tv2[r1]) {
                    ins2(tv1[r1], tk1[r1], tv2[r1], tk2[r1], d2, kk);
                    ins2(tv1[r1], tk1[r1], tv2[r1], tk2[r1], d3, kk + 1);
                }
            }
    }

    // ---- cross-thread reduction (reuse ring buffers; all cp.async must drain) ----
    CP_WAIT0();
    __syncthreads();
    float* sv = (float*)(smem + OFF_BUF(0));       // 4096 floats
    int*   sk = (int*)(smem + OFF_BUF(1));         // 4096 ints
    int*   sidx = (int*)(smem + OFF_BUF(2));       // 128 ints
#pragma unroll
    for (int tr = 0; tr < 4; tr++) {
        int s = (tid * 4 + tr) * 2;
        sv[s] = tv1[tr]; sk[s] = tk1[tr];
        sv[s + 1] = tv2[tr]; sk[s + 1] = tk2[tr];
    }
    __syncthreads();

    if (tid < TM) {
        const int t = tid;
        const int tmw = t >> 5, rloc = t & 31;
        const int mt = rloc >> 4, sub = (rloc >> 3) & 1, l4 = rloc & 7;
        const int tr = mt * 2 + sub;
        float V[4] = {3.4e38f, 3.4e38f, 3.4e38f, 3.4e38f};
        int KI[4] = {0, 0, 0, 0};
#pragma unroll
        for (int ncc = 0; ncc < 4; ncc++)
#pragma unroll
            for (int qq = 0; qq < 4; qq++) {
                int tid2 = (tmw * 4 + ncc) * 32 + l4 * 4 + qq;
                int s = (tid2 * 4 + tr) * 2;
                ins4(V, KI, sv[s], sk[s]);
                ins4(V, KI, sv[s + 1], sk[s + 1]);
            }
        // exact fp32 rescue of approx top-4 -> argmin matches reference
        const float* xr = x + (size_t)(m0 + t) * DIM;
        float bd = 3.4e38f; int bk = 0x7fffffff;
#pragma unroll
        for (int i = 0; i < 4; i++) {
            int k = KI[i];
            float d = g_cnorm[k] - 2.0f * dotrow(xr, cb + (size_t)k * DIM);
            if (d < bd || (d == bd && k < bk)) { bd = d; bk = k; }
        }
        sidx[t] = bk;
        discrete[(size_t)(m0 + t) * KCODES + bk] = 1.0f;
        atomicAdd(&g_cnt[bk], 1.0f);
    }
    __syncthreads();

    // quantized gather + EMA weight numerator scatter
    for (int i = tid; i < TM * DIM; i += NTHR) {
        int t = i >> 6, d = i & 63;
        int k = sidx[t];
        quantized[(size_t)(m0 + t) * DIM + d] = cb[(size_t)k * DIM + d];
        atomicAdd(&g_wsum[k * DIM + d], x[(size_t)(m0 + t) * DIM + d]);
    }
}

// ---------------- kernel 2: EMA finalize ----------------
__global__ void vq_finalize(const float* __restrict__ ema_count,
                            const float* __restrict__ ema_weight,
                            float* __restrict__ ocount,
                            float* __restrict__ oweight,
                            float* __restrict__ ocb) {
    int i = blockIdx.x * blockDim.x + threadIdx.x;
    if (i >= KCODES * DIM) return;
    int k = i >> 6, d = i & 63;
    float cnt  = ema_count[k] * DECAYF + g_cnt[k] * OMDF;
    float norm = (cnt + EPSV) / (BATCHF + (float)KCODES * EPSV) * BATCHF;
    if (d == 0) ocount[k] = norm;
    float w = ema_weight[i] * DECAYF + g_wsum[i] * OMDF;
    oweight[i] = w;
    ocb[i]     = w / norm;
}

// ---------------- launch ----------------
extern "C" void kernel_launch(void* const* d_in, const int* in_sizes, int n_in,
                              void* d_out, int out_size) {
    const float* x  = (const float*)d_in[0];
    const float* cb = (const float*)d_in[1];
    const float* ec = (const float*)d_in[2];
    const float* ew = (const float*)d_in[3];

    float* out       = (float*)d_out;
    float* discrete  = out;                               // N*K
    float* quantized = discrete + (size_t)NTOK * KCODES;  // N*D
    float* ocount    = quantized + (size_t)NTOK * DIM;    // K
    float* oweight   = ocount + KCODES;                   // K*D
    float* ocb       = oweight + (size_t)KCODES * DIM;    // K*D

    vq_prep<<<(KCODES * DIM) / 256, 256>>>(cb);

    cudaFuncSetAttribute((const void*)vq_main,
                         cudaFuncAttributeMaxDynamicSharedMemorySize, SMEM_BYTES);
    vq_main<<<NTOK / TM, NTHR, SMEM_BYTES>>>(x, cb, discrete, quantized);

    vq_finalize<<<(KCODES * DIM + 255) / 256, 256>>>(ec, ew, ocount, oweight, ocb);
}

// round 11
// speedup vs baseline: 1.4378x; 1.2807x over previous
#include <cuda_runtime.h>
#include <cuda_fp16.h>
#include <cstdint>

// VectorQuantizerEMA: N=16384 tokens, K=8192 codes, D=64.
// Outputs (fp32, concat): discrete[N*K], quantized[N*D], new_count[K],
// new_weight[K*D], new_codebook[K*D].

#define NTOK   16384
#define KCODES 8192
#define DIM    64
#define TM     64
#define TN     128
#define NCH    (KCODES / TN)   // 64
#define NTHR   256
#define DECAYF 0.99f
#define OMDF   0.01f
#define EPSV   1e-5f
#define BATCHF 32.0f

// smem layout (bytes): 3-buffer B ring (fp16) + x staging (8KB)
// After the mainloop the ring is reused as reduction scratch.
#define OFF_BUF(i) ((i) * 16384)
#define OFF_X      49152          // x fp16 8KB (64 rows x 128B)
#define SMEM_BYTES 57344

// ---------------- device scratch ----------------
__device__ __align__(128) __half g_cbh[KCODES * DIM];   // fp16 codebook (screening)
__device__ float g_cnorm[KCODES];
__device__ float g_cnt[KCODES];
__device__ float g_wsum[KCODES * DIM];

// ---------------- PTX helpers (base-target legal) ----------------
__device__ __forceinline__ uint32_t smem_u32(const void* p) {
    uint32_t a;
    asm("{ .reg .u64 t; cvta.to.shared.u64 t, %1; cvt.u32.u64 %0, t; }" : "=r"(a) : "l"(p));
    return a;
}
__device__ __forceinline__ void ldsm4(uint32_t* r, uint32_t addr) {
    asm volatile("ldmatrix.sync.aligned.m8n8.x4.shared.b16 {%0,%1,%2,%3}, [%4];"
                 : "=r"(r[0]), "=r"(r[1]), "=r"(r[2]), "=r"(r[3]) : "r"(addr));
}
// fp16 in, fp16 accum (2-reg C/D)
__device__ __forceinline__ void mma16816h(uint32_t* c, const uint32_t* a, uint32_t b0, uint32_t b1) {
    asm volatile("mma.sync.aligned.m16n8k16.row.col.f16.f16.f16.f16 "
                 "{%0,%1}, {%2,%3,%4,%5}, {%6,%7}, {%0,%1};"
                 : "+r"(c[0]), "+r"(c[1])
                 : "r"(a[0]), "r"(a[1]), "r"(a[2]), "r"(a[3]), "r"(b0), "r"(b1));
}
__device__ __forceinline__ void cp16(uint32_t dst, const void* src) {
    asm volatile("cp.async.cg.shared.global [%0], [%1], 16;" :: "r"(dst), "l"(src));
}
#define CP_COMMIT() asm volatile("cp.async.commit_group;" ::: "memory")
#define CP_WAIT1()  asm volatile("cp.async.wait_group 1;" ::: "memory")
#define CP_WAIT0()  asm volatile("cp.async.wait_group 0;" ::: "memory")

__device__ __forceinline__ void ins2(float& V1, int& K1, float& V2, int& K2, float v, int k) {
    if (v < V1) { V2 = V1; K2 = K1; V1 = v; K1 = k; }
    else if (v < V2) { V2 = v; K2 = k; }
}
__device__ __forceinline__ void ins4(float* V, int* KI, float v, int k) {
    if (v < V[3]) {
        if (v < V[1]) {
            V[3] = V[2]; KI[3] = KI[2]; V[2] = V[1]; KI[2] = KI[1];
            if (v < V[0]) { V[1] = V[0]; KI[1] = KI[0]; V[0] = v; KI[0] = k; }
            else { V[1] = v; KI[1] = k; }
        } else {
            if (v < V[2]) { V[3] = V[2]; KI[3] = KI[2]; V[2] = v; KI[2] = k; }
            else { V[3] = v; KI[3] = k; }
        }
    }
}
__device__ __forceinline__ float dotrow(const float* xr, const float* cr) {
    float s = 0.f;
#pragma unroll
    for (int j = 0; j < 16; j++) {
        float4 a = ((const float4*)xr)[j];
        float4 b = ((const float4*)cr)[j];
        s += a.x * b.x + a.y * b.y + a.z * b.z + a.w * b.w;
    }
    return s;
}

// Stage one 128-code chunk (fp16, 16KB) into a smem ring buffer, SW128-swizzled.
__device__ __forceinline__ void stage_chunk(uint32_t sb, int chunk, uint32_t bufoff, int tid) {
    const char* src = (const char*)g_cbh + (size_t)chunk * 16384;
#pragma unroll
    for (int i = 0; i < 4; i++) {
        int gg = tid + i * NTHR;         // 0..1023 uint4s
        int row = gg >> 3, c = gg & 7;
        uint32_t dst = sb + bufoff + row * 128 + ((c * 16) ^ ((row & 7) << 4));
        cp16(dst, src + gg * 16);
    }
}

// ---------------- kernel 0: norms, fp16 cast, zero accumulators ----------------
__global__ void vq_prep(const float* __restrict__ cb) {
    int g = blockIdx.x * blockDim.x + threadIdx.x;   // KCODES*DIM threads
    float v = cb[g];
    g_cbh[g] = __float2half_rn(v);
    g_wsum[g] = 0.0f;
    if (g < KCODES) {
        g_cnt[g] = 0.0f;
        const float4* r = (const float4*)(cb + (size_t)g * DIM);
        float s = 0.0f;
#pragma unroll
        for (int j = 0; j < 16; j++) {
            float4 q = r[j];
            s += q.x * q.x + q.y * q.y + q.z * q.z + q.w * q.w;
        }
        g_cnorm[g] = s;
    }
}

// ---------------- kernel 1: fp16 screening GEMM + top-4 exact rescue + outputs ----------------
// TM=64 tokens/block, 256 threads = 8 warps in a 2m x 4n grid; 2 CTAs/SM.
extern "C" __global__ void __launch_bounds__(NTHR, 2)
vq_main(const float* __restrict__ x, const float* __restrict__ cb,
        float* __restrict__ discrete, float* __restrict__ quantized) {
    extern __shared__ char smem[];
    const uint32_t sb = smem_u32(smem);
    const int tid = threadIdx.x, lane = tid & 31, wid = tid >> 5;
    const int mw = wid >> 2, nc = wid & 3;           // 2 m-warps x 4 n-warps
    const int mbase = mw * 32, nbase = nc * 32;
    const int m0 = blockIdx.x * TM;
    const int qid = lane & 3;

    // ---- stage x tile: fp32 -> fp16, SW128 rows of 128B ----
    for (int i = tid; i < TM * DIM; i += NTHR) {
        int t = i >> 6, d = i & 63;
        float v = x[(size_t)(m0 + t) * DIM + d];
        uint32_t swz = (uint32_t)((d * 2) ^ ((t & 7) << 4));
        *(__half*)(smem + OFF_X + t * 128 + swz) = __float2half_rn(v);
    }
    // ---- prefetch first two B chunks ----
    stage_chunk(sb, 0, OFF_BUF(0), tid); CP_COMMIT();
    stage_chunk(sb, 1, OFF_BUF(1), tid); CP_COMMIT();
    __syncthreads();

    // ---- A fragments loaded once, held in regs ----
    uint32_t afr[2][4][4];   // [m-tile][k-step][reg]
#pragma unroll
    for (int mt = 0; mt < 2; mt++)
#pragma unroll
        for (int ks = 0; ks < 4; ks++) {
            int rowA = mbase + mt * 16 + (lane & 15);
            int byteA = ks * 32 + ((lane & 16) ? 16 : 0);
            ldsm4(afr[mt][ks], sb + OFF_X + rowA * 128 + (byteA ^ ((rowA & 7) << 4)));
        }

    // B ldsm per-lane invariants (warp covers 32 codes => 2 n16 groups)
    const uint32_t bRow = (uint32_t)(nbase + (lane & 7) + ((lane & 16) ? 8 : 0));
    const uint32_t bSwz = (bRow & 7) << 4;
    const uint32_t bByte = (lane & 8) ? 16u : 0u;

    // per-token-row top-2 trackers (4 rows per thread: 2 mt x 2 c-halves)
    float tv1[4], tv2[4];
    int   tk1[4], tk2[4];
#pragma unroll
    for (int i = 0; i < 4; i++) { tv1[i] = 3.4e38f; tv2[i] = 3.4e38f; tk1[i] = 0; tk2[i] = 0; }

    const float4 z4 = make_float4(0.f, 0.f, 0.f, 0.f);
    uint32_t acc[2][4][2];   // f16x2 accumulators [mt][nt][c-half]

    for (int ch = 0; ch < NCH; ch++) {
        CP_WAIT1();
        __syncthreads();   // chunk ch visible; ring buffer (ch+2)%3 free since ch-1

        // stage-ahead: fill (ch+2)%3 while everyone reads ch%3
        if (ch + 2 < NCH) stage_chunk(sb, ch + 2, OFF_BUF((ch + 2) % 3), tid);
        CP_COMMIT();       // unconditional: keeps group counter aligned with chunk index

        // codebook norms for this warp's 32-column slice
        float2 nv[4];
        const float2* cnp = (const float2*)(g_cnorm + ch * TN + nbase);
#pragma unroll
        for (int nt = 0; nt < 4; nt++) nv[nt] = __ldg(&cnp[nt * 4 + qid]);

#pragma unroll
        for (int mt = 0; mt < 2; mt++)
#pragma unroll
            for (int nt = 0; nt < 4; nt++) { acc[mt][nt][0] = 0u; acc[mt][nt][1] = 0u; }

        const uint32_t bufb = OFF_BUF(ch % 3);
#pragma unroll
        for (int ks = 0; ks < 4; ks++) {
            uint32_t bh[2][4];
#pragma unroll
            for (int j = 0; j < 2; j++)
                ldsm4(bh[j], sb + bufb + (bRow + j * 16) * 128 + ((bByte + ks * 32) ^ bSwz));
#pragma unroll
            for (int mt = 0; mt < 2; mt++)
#pragma unroll
                for (int j = 0; j < 2; j++)
#pragma unroll
                    for (int h = 0; h < 2; h++)
                        mma16816h(acc[mt][j * 2 + h], afr[mt][ks], bh[j][h * 2], bh[j][h * 2 + 1]);
        }

        // interleaved streaming zero-fill: 32KB slice of this block's discrete slab
        {
            float4* zb = (float4*)(discrete + (size_t)m0 * KCODES) + (size_t)ch * 2048;
#pragma unroll
            for (int i = 0; i < 8; i++) __stcs(&zb[tid + i * NTHR], z4);
        }

        // gated epilogue: approx dist = ||c||^2 - 2*dot ; track top-2 per token row
        const int kc = ch * TN + nbase + qid * 2;
#pragma unroll
        for (int mt = 0; mt < 2; mt++)
#pragma unroll
            for (int nt = 0; nt < 4; nt++) {
                float2 f01 = __half22float2(*(const __half2*)&acc[mt][nt][0]);  // row r, cols q,q+1
                float2 f23 = __half22float2(*(const __half2*)&acc[mt][nt][1]);  // row r+8
                const int kk = kc + nt * 8;
                float d0 = fmaf(f01.x, -2.0f, nv[nt].x);
                float d1 = fmaf(f01.y, -2.0f, nv[nt].y);
                float d2 = fmaf(f23.x, -2.0f, nv[nt].x);
                float d3 = fmaf(f23.y, -2.0f, nv[nt].y);
                const int r0 = mt * 2, r1 = mt * 2 + 1;
                if (fminf(d0, d1) < tv2[r0]) {
                    ins2(tv1[r0], tk1[r0], tv2[r0], tk2[r0], d0, kk);
                    ins2(tv1[r0], tk1[r0], tv2[r0], tk2[r0], d1, kk + 1);
                }
                if (fminf(d2, d3) < tv2[r1]) {
                    ins2(tv1[r1], tk1[r1], tv2[r1], tk2[r1], d2, kk);
                    ins2(tv1[r1], tk1[r1], tv2[r1], tk2[r1], d3, kk + 1);
                }
            }
    }

    // ---- cross-thread reduction (reuse ring buffers; all cp.async must drain) ----
    CP_WAIT0();
    __syncthreads();
    float* sv = (float*)(smem + OFF_BUF(0));       // 2048 floats
    int*   sk = (int*)(smem + OFF_BUF(1));         // 2048 ints
    int*   sidx = (int*)(smem + OFF_BUF(2));       // 64 ints
#pragma unroll
    for (int tr = 0; tr < 4; tr++) {
        int s = (tid * 4 + tr) * 2;
        sv[s] = tv1[tr]; sk[s] = tk1[tr];
        sv[s + 1] = tv2[tr]; sk[s + 1] = tk2[tr];
    }
    __syncthreads();

    if (tid < TM) {
        const int t = tid;
        const int tmw = t >> 5, rloc = t & 31;       // m-warp, row-in-warp
        const int mt = rloc >> 4, sub = (rloc >> 3) & 1, l4 = rloc & 7;
        const int tr = mt * 2 + sub;
        float V[4] = {3.4e38f, 3.4e38f, 3.4e38f, 3.4e38f};
        int KI[4] = {0, 0, 0, 0};
#pragma unroll
        for (int ncc = 0; ncc < 4; ncc++)
#pragma unroll
            for (int qq = 0; qq < 4; qq++) {
                int tid2 = (tmw * 4 + ncc) * 32 + l4 * 4 + qq;
                int s = (tid2 * 4 + tr) * 2;
                ins4(V, KI, sv[s], sk[s]);
                ins4(V, KI, sv[s + 1], sk[s + 1]);
            }
        // exact fp32 rescue of approx top-4 -> argmin matches reference
        const float* xr = x + (size_t)(m0 + t) * DIM;
        float bd = 3.4e38f; int bk = 0x7fffffff;
#pragma unroll
        for (int i = 0; i < 4; i++) {
            int k = KI[i];
            float d = g_cnorm[k] - 2.0f * dotrow(xr, cb + (size_t)k * DIM);
            if (d < bd || (d == bd && k < bk)) { bd = d; bk = k; }
        }
        sidx[t] = bk;
        discrete[(size_t)(m0 + t) * KCODES + bk] = 1.0f;
        atomicAdd(&g_cnt[bk], 1.0f);
    }
    __syncthreads();

    // quantized gather + EMA weight numerator scatter
    for (int i = tid; i < TM * DIM; i += NTHR) {
        int t = i >> 6, d = i & 63;
        int k = sidx[t];
        quantized[(size_t)(m0 + t) * DIM + d] = cb[(size_t)k * DIM + d];
        atomicAdd(&g_wsum[k * DIM + d], x[(size_t)(m0 + t) * DIM + d]);
    }
}

// ---------------- kernel 2: EMA finalize ----------------
__global__ void vq_finalize(const float* __restrict__ ema_count,
                            const float* __restrict__ ema_weight,
                            float* __restrict__ ocount,
                            float* __restrict__ oweight,
                            float* __restrict__ ocb) {
    int i = blockIdx.x * blockDim.x + threadIdx.x;
    if (i >= KCODES * DIM) return;
    int k = i >> 6, d = i & 63;
    float cnt  = ema_count[k] * DECAYF + g_cnt[k] * OMDF;
    float norm = (cnt + EPSV) / (BATCHF + (float)KCODES * EPSV) * BATCHF;
    if (d == 0) ocount[k] = norm;
    float w = ema_weight[i] * DECAYF + g_wsum[i] * OMDF;
    oweight[i] = w;
    ocb[i]     = w / norm;
}

// ---------------- launch ----------------
extern "C" void kernel_launch(void* const* d_in, const int* in_sizes, int n_in,
                              void* d_out, int out_size) {
    const float* x  = (const float*)d_in[0];
    const float* cb = (const float*)d_in[1];
    const float* ec = (const float*)d_in[2];
    const float* ew = (const float*)d_in[3];

    float* out       = (float*)d_out;
    float* discrete  = out;                               // N*K
    float* quantized = discrete + (size_t)NTOK * KCODES;  // N*D
    float* ocount    = quantized + (size_t)NTOK * DIM;    // K
    float* oweight   = ocount + KCODES;                   // K*D
    float* ocb       = oweight + (size_t)KCODES * DIM;    // K*D

    vq_prep<<<(KCODES * DIM) / 256, 256>>>(cb);

    cudaFuncSetAttribute((const void*)vq_main,
                         cudaFuncAttributeMaxDynamicSharedMemorySize, SMEM_BYTES);
    vq_main<<<NTOK / TM, NTHR, SMEM_BYTES>>>(x, cb, discrete, quantized);

    vq_finalize<<<(KCODES * DIM + 255) / 256, 256>>>(ec, ew, ocount, oweight, ocb);
}